// round 2
// baseline (speedup 1.0000x reference)
#include <cuda_runtime.h>
#include <cstdint>

#define N_PTS      16384
#define B_SZ       4
#define S_SAMPLES  1024
#define K_NB       32
#define C_FEAT     128

#define CEN_OFF    0
#define GX_OFF     (B_SZ * S_SAMPLES * 3)                      // 12288
#define GF_OFF     (GX_OFF + B_SZ * S_SAMPLES * K_NB * 3)     // 405504

#define FPS_C      4                    // cluster size (CTAs per batch)
#define FPS_T      256                  // threads per CTA
#define FPS_PAIRS  8                    // 16 points per thread
#define PTS_PER_CTA (N_PTS / FPS_C)     // 4096

typedef unsigned long long ull;

// ---------------- packed f32x2 helpers (exact per-lane round-to-nearest) ----
__device__ __forceinline__ ull pack2(float lo, float hi) {
    ull r; asm("mov.b64 %0, {%1, %2};" : "=l"(r) : "f"(lo), "f"(hi)); return r;
}
__device__ __forceinline__ void unpack2(ull v, float& lo, float& hi) {
    asm("mov.b64 {%0, %1}, %2;" : "=f"(lo), "=f"(hi) : "l"(v));
}
__device__ __forceinline__ ull addx2(ull a, ull b) {
    ull r; asm("add.rn.f32x2 %0, %1, %2;" : "=l"(r) : "l"(a), "l"(b)); return r;
}
__device__ __forceinline__ ull mulx2(ull a, ull b) {
    ull r; asm("mul.rn.f32x2 %0, %1, %2;" : "=l"(r) : "l"(a), "l"(b)); return r;
}

// ---------------- cluster / mbarrier helpers --------------------------------
__device__ __forceinline__ uint32_t smem_u32(const void* p) {
    uint32_t a;
    asm("{ .reg .u64 t; cvta.to.shared.u64 t, %1; cvt.u32.u64 %0, t; }"
        : "=r"(a) : "l"(p));
    return a;
}
__device__ __forceinline__ uint32_t mapa_u32(uint32_t a, uint32_t rank) {
    uint32_t d;
    asm("mapa.shared::cluster.u32 %0, %1, %2;" : "=r"(d) : "r"(a), "r"(rank));
    return d;
}
__device__ __forceinline__ void mbar_init(uint32_t a, uint32_t cnt) {
    asm volatile("mbarrier.init.shared.b64 [%0], %1;" :: "r"(a), "r"(cnt) : "memory");
}
__device__ __forceinline__ void mbar_arrive_cluster(uint32_t cluster_addr) {
    asm volatile("mbarrier.arrive.release.cluster.shared::cluster.b64 _, [%0];"
                 :: "r"(cluster_addr) : "memory");
}
__device__ __forceinline__ void mbar_wait_parity_cluster(uint32_t a, uint32_t par) {
    uint32_t done;
    do {
        asm volatile(
            "{\n\t.reg .pred p;\n\t"
            "mbarrier.try_wait.parity.acquire.cluster.shared::cta.b64 p, [%1], %2, 0x989680;\n\t"
            "selp.b32 %0, 1, 0, p;\n\t}"
            : "=r"(done) : "r"(a), "r"(par) : "memory");
    } while (!done);
}
__device__ __forceinline__ void st_remote_b64(uint32_t cluster_addr, ull v) {
    asm volatile("st.shared::cluster.b64 [%0], %1;" :: "r"(cluster_addr), "l"(v) : "memory");
}
__device__ __forceinline__ void st_remote_b32(uint32_t cluster_addr, float v) {
    asm volatile("st.shared::cluster.b32 [%0], %1;" :: "r"(cluster_addr), "f"(v) : "memory");
}
__device__ __forceinline__ void cluster_sync_() {
    asm volatile("barrier.cluster.arrive.aligned;" ::: "memory");
    asm volatile("barrier.cluster.wait.aligned;" ::: "memory");
}

// ============================================================================
// FPS: cluster of 4 CTAs per batch, 4096 points per CTA, min_d in registers.
// Per iteration: local update+argmax, warp shfl reduce (key+coords), CTA
// reduce, symmetric all-to-all candidate exchange over DSMEM with mbarrier;
// every CTA reduces the 4 candidate tuples identically.
// Exact argmax w/ jnp tie-break: key = (float_bits(v)<<32) | (0xFFFFFFFF-idx).
// ============================================================================
__global__ __launch_bounds__(FPS_T, 1) __cluster_dims__(FPS_C, 1, 1)
void fps_kernel(const float* __restrict__ xyz, float* __restrict__ out)
{
    __shared__ ull   s_wkey[8];
    __shared__ float s_wx[8], s_wy[8], s_wz[8];
    __shared__ ull   s_gkey[2][FPS_C];      // double-buffered by parity
    __shared__ ull   s_gxy[2][FPS_C];
    __shared__ float s_gz[2][FPS_C];
    __shared__ ull   s_bar;

    const int t    = threadIdx.x;
    const int rank = blockIdx.x;            // == cluster cta rank
    const int b    = blockIdx.y;
    const float* base = xyz + (size_t)b * N_PTS * 3;
    float* cen = out + CEN_OFF + (size_t)b * S_SAMPLES * 3;

    const uint32_t bar_addr = smem_u32(&s_bar);
    if (t == 0) mbar_init(bar_addr, FPS_C);     // 1 local + 3 remote arrivals

    // Register-resident points: pair q holds indices i0 = pbase + 512q, i1 = i0+256.
    // Per-thread point order is ascending -> strict '>' keeps earliest index.
    const int pbase = rank * PTS_PER_CTA + t;
    ull X[FPS_PAIRS], Y[FPS_PAIRS], Z[FPS_PAIRS];
    float M[2 * FPS_PAIRS];
#pragma unroll
    for (int q = 0; q < FPS_PAIRS; ++q) {
        const int i0 = pbase + 512 * q, i1 = i0 + 256;
        X[q] = pack2(base[i0 * 3 + 0], base[i1 * 3 + 0]);
        Y[q] = pack2(base[i0 * 3 + 1], base[i1 * 3 + 1]);
        Z[q] = pack2(base[i0 * 3 + 2], base[i1 * 3 + 2]);
        M[2 * q] = 1e10f; M[2 * q + 1] = 1e10f;
    }

    asm volatile("fence.mbarrier_init.release.cluster;" ::: "memory");
    cluster_sync_();

    float lx = __ldg(base + 0), ly = __ldg(base + 1), lz = __ldg(base + 2);
    if (rank == 0 && t == 0) { cen[0] = lx; cen[1] = ly; cen[2] = lz; }

    const int lane = t & 31, w = t >> 5;

    for (int s = 1; s < S_SAMPLES; ++s) {
        const ull nx = pack2(-lx, -lx);
        const ull ny = pack2(-ly, -ly);
        const ull nz = pack2(-lz, -lz);
        float vmax = -1.0f, wx = 0.f, wy = 0.f, wz = 0.f;
        int imax = 0;
#pragma unroll
        for (int q = 0; q < FPS_PAIRS; ++q) {
            ull dx = addx2(X[q], nx);                 // rn(x - lx)
            ull dy = addx2(Y[q], ny);
            ull dz = addx2(Z[q], nz);
            ull d2 = addx2(addx2(mulx2(dx, dx), mulx2(dy, dy)), mulx2(dz, dz));
            float d0, d1; unpack2(d2, d0, d1);
            float x0, x1, y0, y1, z0, z1;
            unpack2(X[q], x0, x1); unpack2(Y[q], y0, y1); unpack2(Z[q], z0, z1);

            const int i0 = pbase + 512 * q;
            float m0 = fminf(M[2 * q], d0);     M[2 * q] = m0;
            if (m0 > vmax) { vmax = m0; imax = i0; wx = x0; wy = y0; wz = z0; }
            float m1 = fminf(M[2 * q + 1], d1); M[2 * q + 1] = m1;
            if (m1 > vmax) { vmax = m1; imax = i0 + 256; wx = x1; wy = y1; wz = z1; }
        }

        ull key = ((ull)__float_as_uint(vmax) << 32)
                | (unsigned)(0xFFFFFFFFu - (unsigned)imax);
#pragma unroll
        for (int off = 16; off > 0; off >>= 1) {
            ull   ok = __shfl_down_sync(0xFFFFFFFFu, key, off);
            float ox = __shfl_down_sync(0xFFFFFFFFu, wx,  off);
            float oy = __shfl_down_sync(0xFFFFFFFFu, wy,  off);
            float oz = __shfl_down_sync(0xFFFFFFFFu, wz,  off);
            if (ok > key) { key = ok; wx = ox; wy = oy; wz = oz; }
        }
        if (lane == 0) { s_wkey[w] = key; s_wx[w] = wx; s_wy[w] = wy; s_wz[w] = wz; }
        __syncthreads();

        const uint32_t par = (unsigned)(s - 1) & 1u;
        if (w == 0) {
            ull k2 = (lane < 8) ? s_wkey[lane] : 0ull;
            float x2 = (lane < 8) ? s_wx[lane] : 0.f;
            float y2 = (lane < 8) ? s_wy[lane] : 0.f;
            float z2 = (lane < 8) ? s_wz[lane] : 0.f;
#pragma unroll
            for (int off = 4; off > 0; off >>= 1) {
                ull   ok = __shfl_down_sync(0xFFFFFFFFu, k2, off);
                float ox = __shfl_down_sync(0xFFFFFFFFu, x2, off);
                float oy = __shfl_down_sync(0xFFFFFFFFu, y2, off);
                float oz = __shfl_down_sync(0xFFFFFFFFu, z2, off);
                if (ok > k2) { k2 = ok; x2 = ox; y2 = oy; z2 = oz; }
            }
            if (lane == 0) {
                const ull kxy = pack2(x2, y2);
                const uint32_t a_key = smem_u32(&s_gkey[par][rank]);
                const uint32_t a_xy  = smem_u32(&s_gxy[par][rank]);
                const uint32_t a_z   = smem_u32(&s_gz[par][rank]);
#pragma unroll
                for (int p = 0; p < FPS_C; ++p) {
                    const uint32_t rk = mapa_u32(a_key, p);
                    const uint32_t rx = mapa_u32(a_xy,  p);
                    const uint32_t rz = mapa_u32(a_z,   p);
                    st_remote_b64(rk, k2);
                    st_remote_b64(rx, kxy);
                    st_remote_b32(rz, z2);
                    mbar_arrive_cluster(mapa_u32(bar_addr, p));
                }
            }
        }

        mbar_wait_parity_cluster(bar_addr, par);

        // All threads pick the global winner from the 4 candidate tuples.
        ull bk = s_gkey[par][0]; ull bxy = s_gxy[par][0]; float bz = s_gz[par][0];
#pragma unroll
        for (int p = 1; p < FPS_C; ++p) {
            ull k = s_gkey[par][p];
            if (k > bk) { bk = k; bxy = s_gxy[par][p]; bz = s_gz[par][p]; }
        }
        unpack2(bxy, lx, ly); lz = bz;
        if (rank == 0 && t == 0) {
            cen[s * 3 + 0] = lx; cen[s * 3 + 1] = ly; cen[s * 3 + 2] = lz;
        }
    }
    cluster_sync_();   // no CTA exits while peers may still touch its smem
}

// ============================================================================
// Ball query + gather: one warp per centroid, 64 points per ballot iteration,
// early exit at K hits. Scan order == ascending index == reference top_k order.
// ============================================================================
#define BQ_WARPS 8

__global__ __launch_bounds__(BQ_WARPS * 32)
void group_kernel(const float* __restrict__ xyz,
                  const float* __restrict__ feat,
                  float* __restrict__ out)
{
    const int w    = threadIdx.x >> 5;
    const int lane = threadIdx.x & 31;
    const int c    = blockIdx.x * BQ_WARPS + w;          // centroid id
    const int b    = c >> 10;
    const float* base = xyz + (size_t)b * N_PTS * 3;

    const float* cen = out + CEN_OFF + (size_t)c * 3;
    const float cx = __ldg(cen + 0), cy = __ldg(cen + 1), cz = __ldg(cen + 2);
    const float R2 = (float)(0.2 * 0.2);

    __shared__ int s_idx[BQ_WARPS][K_NB];

    int cnt = 0;
    for (int j = 0; j < N_PTS / 64 && cnt < K_NB; ++j) {
        const int p0 = j * 64 + lane;
        const int p1 = p0 + 32;
        const float dx0 = __fadd_rn(cx, -base[p0 * 3 + 0]);
        const float dy0 = __fadd_rn(cy, -base[p0 * 3 + 1]);
        const float dz0 = __fadd_rn(cz, -base[p0 * 3 + 2]);
        const float sq0 = __fadd_rn(__fadd_rn(__fmul_rn(dx0, dx0), __fmul_rn(dy0, dy0)),
                                    __fmul_rn(dz0, dz0));
        const float dx1 = __fadd_rn(cx, -base[p1 * 3 + 0]);
        const float dy1 = __fadd_rn(cy, -base[p1 * 3 + 1]);
        const float dz1 = __fadd_rn(cz, -base[p1 * 3 + 2]);
        const float sq1 = __fadd_rn(__fadd_rn(__fmul_rn(dx1, dx1), __fmul_rn(dy1, dy1)),
                                    __fmul_rn(dz1, dz1));
        const bool h0 = (sq0 <= R2);
        const bool h1 = (sq1 <= R2);
        const unsigned m0 = __ballot_sync(0xFFFFFFFFu, h0);
        const unsigned m1 = __ballot_sync(0xFFFFFFFFu, h1);
        if (h0) {
            const int pos = cnt + __popc(m0 & ((1u << lane) - 1u));
            if (pos < K_NB) s_idx[w][pos] = p0;
        }
        const int c1 = cnt + __popc(m0);
        if (h1) {
            const int pos = c1 + __popc(m1 & ((1u << lane) - 1u));
            if (pos < K_NB) s_idx[w][pos] = p1;
        }
        cnt = c1 + __popc(m1);
    }
    __syncwarp();
    const int first = s_idx[w][0];          // >=1 hit guaranteed (centroid itself)
    if (cnt < K_NB && lane >= cnt) s_idx[w][lane] = first;
    __syncwarp();

    // grouped_xyz (centered): one neighbor per lane
    {
        const int gi = s_idx[w][lane];
        float* go = out + GX_OFF + ((size_t)c * K_NB + lane) * 3;
        go[0] = __fadd_rn(base[gi * 3 + 0], -cx);
        go[1] = __fadd_rn(base[gi * 3 + 1], -cy);
        go[2] = __fadd_rn(base[gi * 3 + 2], -cz);
    }

    // grouped features: K neighbors x 128 floats, float4 per lane per row
    const float4* f4 = (const float4*)feat;
    float4* o4 = (float4*)(out + GF_OFF) + (size_t)c * K_NB * (C_FEAT / 4);
#pragma unroll 4
    for (int k = 0; k < K_NB; ++k) {
        const int gi = s_idx[w][k];
        o4[(size_t)k * (C_FEAT / 4) + lane] =
            f4[((size_t)b * N_PTS + gi) * (C_FEAT / 4) + lane];
    }
}

// ============================================================================
extern "C" void kernel_launch(void* const* d_in, const int* in_sizes, int n_in,
                              void* d_out, int out_size)
{
    const float* xyz  = (const float*)d_in[0];
    const float* feat = (const float*)d_in[1];
    if (n_in >= 2 && in_sizes[0] > in_sizes[1]) {   // defensive: xyz is smaller
        const float* tmp = xyz; xyz = feat; feat = tmp;
    }
    float* out = (float*)d_out;

    fps_kernel<<<dim3(FPS_C, B_SZ), FPS_T>>>(xyz, out);
    group_kernel<<<(B_SZ * S_SAMPLES) / BQ_WARPS, BQ_WARPS * 32>>>(xyz, feat, out);
}